// round 2
// baseline (speedup 1.0000x reference)
#include <cuda_runtime.h>
#include <math.h>
#include <stdint.h>

#define BATCH   2048
#define LSEQ    512
#define DIN     32
#define CD      128
#define NSTEPS  32
#define NT      65
#define INF     3328
#define HIDF    256
#define OUTF    3072

__device__ float g_u[(size_t)NT * BATCH * CD];
__device__ float g_z[BATCH * CD];
__device__ float g_hin[(size_t)BATCH * INF];
__device__ float g_h1[BATCH * HIDF];
__device__ float g_h2[BATCH * HIDF];
__device__ float g_WcT[DIN * CD];
__device__ float g_WzT[DIN * CD];
__device__ float g_cc[CD];
__device__ float g_cz[CD];

__device__ __forceinline__ float siluf(float x) { return x / (1.0f + __expf(-x)); }

// ---------------- K0: fold projection into ODE input / z0 maps ----------------
__global__ void fold_kernel(const float* __restrict__ w1, const float* __restrict__ b1,
                            const float* __restrict__ xpw, const float* __restrict__ xpb,
                            const float* __restrict__ z0w, const float* __restrict__ z0b) {
    int t = threadIdx.x;
    int j = t & 127;
    bool isC = (t < 128);
    int d0 = blockIdx.x * 4;
    const float* row = isC ? (w1 + j * 256 + 128) : (z0w + j * 128);
    float a0 = 0.f, a1 = 0.f, a2 = 0.f, a3 = 0.f, cb = 0.f;
    for (int i = 0; i < 128; ++i) {
        float wv = row[i];
        const float* xr = xpw + i * 32 + d0;
        a0 = fmaf(wv, xr[0], a0); a1 = fmaf(wv, xr[1], a1);
        a2 = fmaf(wv, xr[2], a2); a3 = fmaf(wv, xr[3], a3);
        if (blockIdx.x == 0) cb = fmaf(wv, xpb[i], cb);
    }
    float* WT = isC ? g_WcT : g_WzT;
    WT[(d0 + 0) * CD + j] = a0; WT[(d0 + 1) * CD + j] = a1;
    WT[(d0 + 2) * CD + j] = a2; WT[(d0 + 3) * CD + j] = a3;
    if (blockIdx.x == 0) { if (isC) g_cc[j] = cb + b1[j]; else g_cz[j] = cb + z0b[j]; }
}

// ---------------- K1: interp(past) @ foldedW for 65 time slots + z0 ----------------
__global__ void interp_proj_kernel(const float* __restrict__ past) {
    __shared__ float p_sh[64][33];
    __shared__ float wt_sh[DIN][CD];
    int ts = blockIdx.y;
    int b0 = blockIdx.x * 64;
    int t = threadIdx.x;

    const float *WT, *cv;
    float* outp;
    int i0, i1; float w;
    if (ts < NT) {
        float pos = (float)ts * (511.0f / 64.0f);
        i0 = (int)pos; if (i0 > 511) i0 = 511;
        i1 = i0 + 1;   if (i1 > 511) i1 = 511;
        w = pos - (float)i0;
        WT = g_WcT; cv = g_cc; outp = g_u + (size_t)ts * BATCH * CD;
    } else {
        i0 = 0; i1 = 0; w = 0.f;
        WT = g_WzT; cv = g_cz; outp = g_z;
    }
    for (int idx = t; idx < DIN * CD; idx += 256)
        wt_sh[idx >> 7][idx & 127] = WT[idx];
    for (int idx = t; idx < 64 * DIN; idx += 256) {
        int r = idx >> 5, d = idx & 31;
        const float* pb = past + (size_t)(b0 + r) * LSEQ * DIN + d;
        float a = pb[(size_t)i0 * DIN];
        float b = pb[(size_t)i1 * DIN];
        p_sh[r][d] = (1.0f - w) * a + w * b;
    }
    __syncthreads();

    int jt = t & 31, j0 = jt * 4, rg = t >> 5;
    float acc[8][4];
#pragma unroll
    for (int r = 0; r < 8; ++r) { acc[r][0]=acc[r][1]=acc[r][2]=acc[r][3]=0.f; }
#pragma unroll 4
    for (int d = 0; d < DIN; ++d) {
        float4 w4 = *(const float4*)(&wt_sh[d][j0]);
#pragma unroll
        for (int r = 0; r < 8; ++r) {
            float x = p_sh[rg * 8 + r][d];
            acc[r][0] = fmaf(w4.x, x, acc[r][0]);
            acc[r][1] = fmaf(w4.y, x, acc[r][1]);
            acc[r][2] = fmaf(w4.z, x, acc[r][2]);
            acc[r][3] = fmaf(w4.w, x, acc[r][3]);
        }
    }
    float4 cv4 = *(const float4*)(cv + j0);
#pragma unroll
    for (int r = 0; r < 8; ++r) {
        float4 o;
        o.x = acc[r][0] + cv4.x; o.y = acc[r][1] + cv4.y;
        o.z = acc[r][2] + cv4.z; o.w = acc[r][3] + cv4.w;
        *(float4*)(outp + (size_t)(b0 + rg * 8 + r) * CD + j0) = o;
    }
}

// ---------------- K2: persistent RK4 ODE kernel ----------------
#define ODE_SMEM_FLOATS (3 * CD * CD + 2 * 16 * CD + 2 * CD)
#define ODE_SMEM_BYTES  (ODE_SMEM_FLOATS * 4)

__device__ __forceinline__ void stage_mm(const float* __restrict__ in,
                                         const float* __restrict__ ws,
                                         int r0, int j0, float o0[4], float o1[4]) {
    o0[0]=o0[1]=o0[2]=o0[3]=0.f;
    o1[0]=o1[1]=o1[2]=o1[3]=0.f;
    const float* ir0 = in + r0 * CD;
    const float* ir1 = ir0 + CD;
#pragma unroll 4
    for (int kk = 0; kk < CD; ++kk) {
        float4 w4 = *(const float4*)(ws + kk * CD + j0);
        float x0 = ir0[kk];
        float x1 = ir1[kk];
        o0[0] = fmaf(w4.x, x0, o0[0]); o0[1] = fmaf(w4.y, x0, o0[1]);
        o0[2] = fmaf(w4.z, x0, o0[2]); o0[3] = fmaf(w4.w, x0, o0[3]);
        o1[0] = fmaf(w4.x, x1, o1[0]); o1[1] = fmaf(w4.y, x1, o1[1]);
        o1[2] = fmaf(w4.z, x1, o1[2]); o1[3] = fmaf(w4.w, x1, o1[3]);
    }
}

__global__ void __launch_bounds__(256, 1) ode_kernel(
    const float* __restrict__ w1, const float* __restrict__ w2, const float* __restrict__ b2,
    const float* __restrict__ w3, const float* __restrict__ b3,
    const float* __restrict__ lg, const float* __restrict__ lb) {
    extern __shared__ float sm[];
    float* wA = sm;
    float* wB = wA + CD * CD;
    float* wC = wB + CD * CD;
    float* bufA = wC + CD * CD;
    float* bufB = bufA + 16 * CD;
    float* lngs = bufB + 16 * CD;
    float* lnbs = lngs + CD;

    int t = threadIdx.x;
    int b0 = blockIdx.x * 16;

    for (int idx = t; idx < CD * CD; idx += 256) {
        int j = idx >> 7, k = idx & 127;
        wA[k * CD + j] = w1[j * 256 + k];
        wB[k * CD + j] = w2[j * 128 + k];
        wC[k * CD + j] = w3[j * 128 + k];
    }
    if (t < CD) { lngs[t] = lg[t]; lnbs[t] = lb[t]; }
    __syncthreads();

    int jt = t & 31, j0 = jt * 4, rg = t >> 5, r0 = rg * 2;
    float4 b2v = *(const float4*)(b2 + j0);
    float4 b3v = *(const float4*)(b3 + j0);
    float4 g4  = *(const float4*)(lngs + j0);
    float4 bq4 = *(const float4*)(lnbs + j0);

    float zb0[4], zb1[4], zc0[4], zc1[4], ac0[4], ac1[4];
    {
        float4 za = *(const float4*)(g_z + (size_t)(b0 + r0) * CD + j0);
        float4 zq = *(const float4*)(g_z + (size_t)(b0 + r0 + 1) * CD + j0);
        zb0[0]=za.x; zb0[1]=za.y; zb0[2]=za.z; zb0[3]=za.w;
        zb1[0]=zq.x; zb1[1]=zq.y; zb1[2]=zq.z; zb1[3]=zq.w;
#pragma unroll
        for (int d = 0; d < 4; ++d) { zc0[d]=zb0[d]; zc1[d]=zb1[d]; }
    }

    const float dt = 1.0f / 32.0f, hdt = dt * 0.5f, dt6 = dt / 6.0f;

    for (int step = 0; step < NSTEPS; ++step) {
#pragma unroll 1
        for (int e = 0; e < 4; ++e) {
            int m = 2 * step + ((e == 0) ? 0 : ((e == 3) ? 2 : 1));
            const float* up = g_u + ((size_t)m * BATCH + (b0 + r0)) * CD + j0;
            float4 u0 = *(const float4*)up;
            float4 u1 = *(const float4*)(up + CD);

            // LayerNorm of zc (rows live in this warp's registers)
            {
                float s0 = zc0[0]+zc0[1]+zc0[2]+zc0[3];
                float q0 = zc0[0]*zc0[0]+zc0[1]*zc0[1]+zc0[2]*zc0[2]+zc0[3]*zc0[3];
                float s1 = zc1[0]+zc1[1]+zc1[2]+zc1[3];
                float q1 = zc1[0]*zc1[0]+zc1[1]*zc1[1]+zc1[2]*zc1[2]+zc1[3]*zc1[3];
#pragma unroll
                for (int o = 16; o > 0; o >>= 1) {
                    s0 += __shfl_xor_sync(0xffffffffu, s0, o);
                    q0 += __shfl_xor_sync(0xffffffffu, q0, o);
                    s1 += __shfl_xor_sync(0xffffffffu, s1, o);
                    q1 += __shfl_xor_sync(0xffffffffu, q1, o);
                }
                float mu0 = s0 * (1.0f/128.0f), mu1 = s1 * (1.0f/128.0f);
                float rs0 = rsqrtf(q0 * (1.0f/128.0f) - mu0*mu0 + 1e-5f);
                float rs1 = rsqrtf(q1 * (1.0f/128.0f) - mu1*mu1 + 1e-5f);
                float4 n0, n1;
                n0.x=(zc0[0]-mu0)*rs0*g4.x+bq4.x; n0.y=(zc0[1]-mu0)*rs0*g4.y+bq4.y;
                n0.z=(zc0[2]-mu0)*rs0*g4.z+bq4.z; n0.w=(zc0[3]-mu0)*rs0*g4.w+bq4.w;
                n1.x=(zc1[0]-mu1)*rs1*g4.x+bq4.x; n1.y=(zc1[1]-mu1)*rs1*g4.y+bq4.y;
                n1.z=(zc1[2]-mu1)*rs1*g4.z+bq4.z; n1.w=(zc1[3]-mu1)*rs1*g4.w+bq4.w;
                *(float4*)(bufA + r0 * CD + j0) = n0;
                *(float4*)(bufA + (r0 + 1) * CD + j0) = n1;
            }
            __syncwarp();

            float o0[4], o1[4];
            stage_mm(bufA, wA, r0, j0, o0, o1);           // stage 1
            {
                float4 h0, h1;
                h0.x=siluf(o0[0]+u0.x); h0.y=siluf(o0[1]+u0.y);
                h0.z=siluf(o0[2]+u0.z); h0.w=siluf(o0[3]+u0.w);
                h1.x=siluf(o1[0]+u1.x); h1.y=siluf(o1[1]+u1.y);
                h1.z=siluf(o1[2]+u1.z); h1.w=siluf(o1[3]+u1.w);
                *(float4*)(bufB + r0 * CD + j0) = h0;
                *(float4*)(bufB + (r0 + 1) * CD + j0) = h1;
            }
            __syncwarp();
            stage_mm(bufB, wB, r0, j0, o0, o1);           // stage 2
            {
                float4 h0, h1;
                h0.x=siluf(o0[0]+b2v.x); h0.y=siluf(o0[1]+b2v.y);
                h0.z=siluf(o0[2]+b2v.z); h0.w=siluf(o0[3]+b2v.w);
                h1.x=siluf(o1[0]+b2v.x); h1.y=siluf(o1[1]+b2v.y);
                h1.z=siluf(o1[2]+b2v.z); h1.w=siluf(o1[3]+b2v.w);
                *(float4*)(bufA + r0 * CD + j0) = h0;
                *(float4*)(bufA + (r0 + 1) * CD + j0) = h1;
            }
            __syncwarp();
            stage_mm(bufA, wC, r0, j0, o0, o1);           // stage 3 -> k
            float k0v[4], k1v[4];
            k0v[0]=o0[0]+b3v.x; k0v[1]=o0[1]+b3v.y; k0v[2]=o0[2]+b3v.z; k0v[3]=o0[3]+b3v.w;
            k1v[0]=o1[0]+b3v.x; k1v[1]=o1[1]+b3v.y; k1v[2]=o1[2]+b3v.z; k1v[3]=o1[3]+b3v.w;

            if (e == 0) {
#pragma unroll
                for (int d = 0; d < 4; ++d) {
                    ac0[d]=k0v[d]; ac1[d]=k1v[d];
                    zc0[d]=zb0[d]+hdt*k0v[d]; zc1[d]=zb1[d]+hdt*k1v[d];
                }
            } else if (e == 1) {
#pragma unroll
                for (int d = 0; d < 4; ++d) {
                    ac0[d]+=2.0f*k0v[d]; ac1[d]+=2.0f*k1v[d];
                    zc0[d]=zb0[d]+hdt*k0v[d]; zc1[d]=zb1[d]+hdt*k1v[d];
                }
            } else if (e == 2) {
#pragma unroll
                for (int d = 0; d < 4; ++d) {
                    ac0[d]+=2.0f*k0v[d]; ac1[d]+=2.0f*k1v[d];
                    zc0[d]=zb0[d]+dt*k0v[d]; zc1[d]=zb1[d]+dt*k1v[d];
                }
            } else {
#pragma unroll
                for (int d = 0; d < 4; ++d) {
                    ac0[d]+=k0v[d]; ac1[d]+=k1v[d];
                    zb0[d]+=dt6*ac0[d]; zb1[d]+=dt6*ac1[d];
                    zc0[d]=zb0[d]; zc1[d]=zb1[d];
                }
            }
            __syncwarp();
        }
    }
    *(float4*)(g_z + (size_t)(b0 + r0) * CD + j0)     = make_float4(zb0[0],zb0[1],zb0[2],zb0[3]);
    *(float4*)(g_z + (size_t)(b0 + r0 + 1) * CD + j0) = make_float4(zb1[0],zb1[1],zb1[2],zb1[3]);
}

// ---------------- K3: concat [x_flat | cond | time_emb] ----------------
__global__ void build_in_kernel(const float* __restrict__ x_t, const int* __restrict__ tvec) {
    int b = blockIdx.x;
    int t = threadIdx.x;
    float* dst = g_hin + (size_t)b * INF;
    const float* src = x_t + (size_t)b * OUTF;
    for (int i = t; i < OUTF / 4; i += 256)
        ((float4*)dst)[i] = ((const float4*)src)[i];
    if (t < CD / 4)
        ((float4*)(dst + OUTF))[t] = ((const float4*)(g_z + (size_t)b * CD))[t];
    if (t < CD) {
        float tf = (float)tvec[b];
        int i = t & 63;
        float f = expf(-9.210340371976184f * (float)i / 63.0f);
        float arg = tf * f;
        dst[OUTF + CD + t] = (t < 64) ? sinf(arg) : cosf(arg);
    }
}

// ---------------- K4: tiled SGEMM  C = act(A @ W^T + bias) ----------------
template <bool SILU>
__global__ void __launch_bounds__(128) gemm_kernel(const float* __restrict__ A,
                                                   const float* __restrict__ W,
                                                   const float* __restrict__ bias,
                                                   float* __restrict__ C,
                                                   int M, int N, int K) {
    __shared__ float As[16][68];
    __shared__ float Ws[16][68];
    int t = threadIdx.x;
    int bm0 = blockIdx.y * 64, bn0 = blockIdx.x * 64;
    int tm = t >> 4, tn = t & 15;
    int m0 = tm * 8, n0 = tn * 4;
    float acc[8][4];
#pragma unroll
    for (int i = 0; i < 8; ++i) { acc[i][0]=acc[i][1]=acc[i][2]=acc[i][3]=0.f; }

    for (int k0 = 0; k0 < K; k0 += 16) {
#pragma unroll
        for (int it = 0; it < 2; ++it) {
            int r = it * 32 + (t >> 2);
            int c = (t & 3) * 4;
            float4 va = *(const float4*)(A + (size_t)(bm0 + r) * K + k0 + c);
            As[c+0][r]=va.x; As[c+1][r]=va.y; As[c+2][r]=va.z; As[c+3][r]=va.w;
            float4 vw = *(const float4*)(W + (size_t)(bn0 + r) * K + k0 + c);
            Ws[c+0][r]=vw.x; Ws[c+1][r]=vw.y; Ws[c+2][r]=vw.z; Ws[c+3][r]=vw.w;
        }
        __syncthreads();
#pragma unroll
        for (int kk = 0; kk < 16; ++kk) {
            float4 wv = *(const float4*)(&Ws[kk][n0]);
            float4 al = *(const float4*)(&As[kk][m0]);
            float4 ah = *(const float4*)(&As[kk][m0 + 4]);
            float a_[8] = { al.x, al.y, al.z, al.w, ah.x, ah.y, ah.z, ah.w };
#pragma unroll
            for (int i = 0; i < 8; ++i) {
                acc[i][0] = fmaf(a_[i], wv.x, acc[i][0]);
                acc[i][1] = fmaf(a_[i], wv.y, acc[i][1]);
                acc[i][2] = fmaf(a_[i], wv.z, acc[i][2]);
                acc[i][3] = fmaf(a_[i], wv.w, acc[i][3]);
            }
        }
        __syncthreads();
    }
    float4 bv = *(const float4*)(bias + bn0 + n0);
#pragma unroll
    for (int i = 0; i < 8; ++i) {
        float4 o;
        o.x = acc[i][0] + bv.x; o.y = acc[i][1] + bv.y;
        o.z = acc[i][2] + bv.z; o.w = acc[i][3] + bv.w;
        if (SILU) {
            o.x = siluf(o.x); o.y = siluf(o.y); o.z = siluf(o.z); o.w = siluf(o.w);
        }
        *(float4*)(C + (size_t)(bm0 + m0 + i) * N + bn0 + n0) = o;
    }
}

// ---------------- launch ----------------
extern "C" void kernel_launch(void* const* d_in, const int* in_sizes, int n_in,
                              void* d_out, int out_size) {
    const float* x_t  = (const float*)d_in[0];
    const float* past = (const float*)d_in[1];
    const int*   tv   = (const int*)d_in[2];
    const float* xpw  = (const float*)d_in[3];
    const float* xpb  = (const float*)d_in[4];
    const float* z0w  = (const float*)d_in[5];
    const float* z0b  = (const float*)d_in[6];
    const float* lng  = (const float*)d_in[7];
    const float* lnb  = (const float*)d_in[8];
    const float* w1   = (const float*)d_in[9];
    const float* b1   = (const float*)d_in[10];
    const float* w2   = (const float*)d_in[11];
    const float* b2   = (const float*)d_in[12];
    const float* w3   = (const float*)d_in[13];
    const float* b3   = (const float*)d_in[14];
    const float* fw1  = (const float*)d_in[15];
    const float* fb1  = (const float*)d_in[16];
    const float* fw2  = (const float*)d_in[17];
    const float* fb2  = (const float*)d_in[18];
    const float* fw3  = (const float*)d_in[19];
    const float* fb3  = (const float*)d_in[20];
    float* out = (float*)d_out;

    static int smem_set = 0;
    if (!smem_set) {
        cudaFuncSetAttribute(ode_kernel, cudaFuncAttributeMaxDynamicSharedMemorySize, ODE_SMEM_BYTES);
        smem_set = 1;
    }

    fold_kernel<<<8, 256>>>(w1, b1, xpw, xpb, z0w, z0b);
    interp_proj_kernel<<<dim3(32, NT + 1), 256>>>(past);
    ode_kernel<<<BATCH / 16, 256, ODE_SMEM_BYTES>>>(w1, w2, b2, w3, b3, lng, lnb);
    build_in_kernel<<<BATCH, 256>>>(x_t, tv);

    float* h1p; cudaGetSymbolAddress((void**)&h1p, g_h1);
    float* h2p; cudaGetSymbolAddress((void**)&h2p, g_h2);
    float* hinp; cudaGetSymbolAddress((void**)&hinp, g_hin);

    gemm_kernel<true ><<<dim3(HIDF / 64, BATCH / 64), 128>>>(hinp, fw1, fb1, h1p, BATCH, HIDF, INF);
    gemm_kernel<true ><<<dim3(HIDF / 64, BATCH / 64), 128>>>(h1p,  fw2, fb2, h2p, BATCH, HIDF, HIDF);
    gemm_kernel<false><<<dim3(OUTF / 64, BATCH / 64), 128>>>(h2p,  fw3, fb3, out, BATCH, OUTF, HIDF);
}

// round 4
// speedup vs baseline: 1.0012x; 1.0012x over previous
#include <cuda_runtime.h>
#include <math.h>
#include <stdint.h>

#define BATCH   2048
#define LSEQ    512
#define DIN     32
#define CD      128
#define NSTEPS  32
#define NT      65
#define INF     3328
#define HIDF    256
#define OUTF    3072

__device__ float g_u[(size_t)NT * BATCH * CD];
__device__ float g_z[BATCH * CD];
__device__ float g_hin[(size_t)BATCH * INF];
__device__ float g_h1[BATCH * HIDF];
__device__ float g_h2[BATCH * HIDF];
__device__ float g_WcT[DIN * CD];
__device__ float g_WzT[DIN * CD];
__device__ float g_cc[CD];
__device__ float g_cz[CD];

__device__ __forceinline__ float siluf(float x) { return x / (1.0f + __expf(-x)); }

// ---------------- K0: fold projection into ODE input / z0 maps ----------------
__global__ void fold_kernel(const float* __restrict__ w1, const float* __restrict__ b1,
                            const float* __restrict__ xpw, const float* __restrict__ xpb,
                            const float* __restrict__ z0w, const float* __restrict__ z0b) {
    int t = threadIdx.x;
    int j = t & 127;
    bool isC = (t < 128);
    int d0 = blockIdx.x * 4;
    const float* row = isC ? (w1 + j * 256 + 128) : (z0w + j * 128);
    float a0 = 0.f, a1 = 0.f, a2 = 0.f, a3 = 0.f, cb = 0.f;
    for (int i = 0; i < 128; ++i) {
        float wv = row[i];
        const float* xr = xpw + i * 32 + d0;
        a0 = fmaf(wv, xr[0], a0); a1 = fmaf(wv, xr[1], a1);
        a2 = fmaf(wv, xr[2], a2); a3 = fmaf(wv, xr[3], a3);
        if (blockIdx.x == 0) cb = fmaf(wv, xpb[i], cb);
    }
    float* WT = isC ? g_WcT : g_WzT;
    WT[(d0 + 0) * CD + j] = a0; WT[(d0 + 1) * CD + j] = a1;
    WT[(d0 + 2) * CD + j] = a2; WT[(d0 + 3) * CD + j] = a3;
    if (blockIdx.x == 0) { if (isC) g_cc[j] = cb + b1[j]; else g_cz[j] = cb + z0b[j]; }
}

// ---------------- K1: interp(past) @ foldedW for 65 time slots + z0 ----------------
__global__ void interp_proj_kernel(const float* __restrict__ past) {
    __shared__ float p_sh[64][33];
    __shared__ float wt_sh[DIN][CD];
    int ts = blockIdx.y;
    int b0 = blockIdx.x * 64;
    int t = threadIdx.x;

    const float *WT, *cv;
    float* outp;
    int i0, i1; float w;
    if (ts < NT) {
        float pos = (float)ts * (511.0f / 64.0f);
        i0 = (int)pos; if (i0 > 511) i0 = 511;
        i1 = i0 + 1;   if (i1 > 511) i1 = 511;
        w = pos - (float)i0;
        WT = g_WcT; cv = g_cc; outp = g_u + (size_t)ts * BATCH * CD;
    } else {
        i0 = 0; i1 = 0; w = 0.f;
        WT = g_WzT; cv = g_cz; outp = g_z;
    }
    for (int idx = t; idx < DIN * CD; idx += 256)
        wt_sh[idx >> 7][idx & 127] = WT[idx];
    for (int idx = t; idx < 64 * DIN; idx += 256) {
        int r = idx >> 5, d = idx & 31;
        const float* pb = past + (size_t)(b0 + r) * LSEQ * DIN + d;
        float a = pb[(size_t)i0 * DIN];
        float b = pb[(size_t)i1 * DIN];
        p_sh[r][d] = (1.0f - w) * a + w * b;
    }
    __syncthreads();

    int jt = t & 31, j0 = jt * 4, rg = t >> 5;
    float acc[8][4];
#pragma unroll
    for (int r = 0; r < 8; ++r) { acc[r][0]=acc[r][1]=acc[r][2]=acc[r][3]=0.f; }
#pragma unroll 4
    for (int d = 0; d < DIN; ++d) {
        float4 w4 = *(const float4*)(&wt_sh[d][j0]);
#pragma unroll
        for (int r = 0; r < 8; ++r) {
            float x = p_sh[rg * 8 + r][d];
            acc[r][0] = fmaf(w4.x, x, acc[r][0]);
            acc[r][1] = fmaf(w4.y, x, acc[r][1]);
            acc[r][2] = fmaf(w4.z, x, acc[r][2]);
            acc[r][3] = fmaf(w4.w, x, acc[r][3]);
        }
    }
    float4 cv4 = *(const float4*)(cv + j0);
#pragma unroll
    for (int r = 0; r < 8; ++r) {
        float4 o;
        o.x = acc[r][0] + cv4.x; o.y = acc[r][1] + cv4.y;
        o.z = acc[r][2] + cv4.z; o.w = acc[r][3] + cv4.w;
        *(float4*)(outp + (size_t)(b0 + rg * 8 + r) * CD + j0) = o;
    }
}

// ---------------- K2: persistent RK4 ODE kernel ----------------
#define ODE_SMEM_FLOATS (3 * CD * CD + 2 * 16 * CD + 2 * CD)
#define ODE_SMEM_BYTES  (ODE_SMEM_FLOATS * 4)

__device__ __forceinline__ void stage_mm(const float* __restrict__ in,
                                         const float* __restrict__ ws,
                                         int r0, int j0, float o0[4], float o1[4]) {
    o0[0]=o0[1]=o0[2]=o0[3]=0.f;
    o1[0]=o1[1]=o1[2]=o1[3]=0.f;
    const float* ir0 = in + r0 * CD;
    const float* ir1 = ir0 + CD;
#pragma unroll 4
    for (int kk = 0; kk < CD; ++kk) {
        float4 w4 = *(const float4*)(ws + kk * CD + j0);
        float x0 = ir0[kk];
        float x1 = ir1[kk];
        o0[0] = fmaf(w4.x, x0, o0[0]); o0[1] = fmaf(w4.y, x0, o0[1]);
        o0[2] = fmaf(w4.z, x0, o0[2]); o0[3] = fmaf(w4.w, x0, o0[3]);
        o1[0] = fmaf(w4.x, x1, o1[0]); o1[1] = fmaf(w4.y, x1, o1[1]);
        o1[2] = fmaf(w4.z, x1, o1[2]); o1[3] = fmaf(w4.w, x1, o1[3]);
    }
}

__global__ void __launch_bounds__(256, 1) ode_kernel(
    const float* __restrict__ w1, const float* __restrict__ w2, const float* __restrict__ b2,
    const float* __restrict__ w3, const float* __restrict__ b3,
    const float* __restrict__ lg, const float* __restrict__ lb) {
    extern __shared__ float sm[];
    float* wA = sm;
    float* wB = wA + CD * CD;
    float* wC = wB + CD * CD;
    float* bufA = wC + CD * CD;
    float* bufB = bufA + 16 * CD;
    float* lngs = bufB + 16 * CD;
    float* lnbs = lngs + CD;

    int t = threadIdx.x;
    int b0 = blockIdx.x * 16;

    for (int idx = t; idx < CD * CD; idx += 256) {
        int j = idx >> 7, k = idx & 127;
        wA[k * CD + j] = w1[j * 256 + k];
        wB[k * CD + j] = w2[j * 128 + k];
        wC[k * CD + j] = w3[j * 128 + k];
    }
    if (t < CD) { lngs[t] = lg[t]; lnbs[t] = lb[t]; }
    __syncthreads();

    int jt = t & 31, j0 = jt * 4, rg = t >> 5, r0 = rg * 2;
    float4 b2v = *(const float4*)(b2 + j0);
    float4 b3v = *(const float4*)(b3 + j0);
    float4 g4  = *(const float4*)(lngs + j0);
    float4 bq4 = *(const float4*)(lnbs + j0);

    float zb0[4], zb1[4], zc0[4], zc1[4], ac0[4], ac1[4];
    {
        float4 za = *(const float4*)(g_z + (size_t)(b0 + r0) * CD + j0);
        float4 zq = *(const float4*)(g_z + (size_t)(b0 + r0 + 1) * CD + j0);
        zb0[0]=za.x; zb0[1]=za.y; zb0[2]=za.z; zb0[3]=za.w;
        zb1[0]=zq.x; zb1[1]=zq.y; zb1[2]=zq.z; zb1[3]=zq.w;
#pragma unroll
        for (int d = 0; d < 4; ++d) { zc0[d]=zb0[d]; zc1[d]=zb1[d]; }
    }

    const float dt = 1.0f / 32.0f, hdt = dt * 0.5f, dt6 = dt / 6.0f;

    for (int step = 0; step < NSTEPS; ++step) {
#pragma unroll 1
        for (int e = 0; e < 4; ++e) {
            int m = 2 * step + ((e == 0) ? 0 : ((e == 3) ? 2 : 1));
            const float* up = g_u + ((size_t)m * BATCH + (b0 + r0)) * CD + j0;
            float4 u0 = *(const float4*)up;
            float4 u1 = *(const float4*)(up + CD);

            // LayerNorm of zc (rows live in this warp's registers)
            {
                float s0 = zc0[0]+zc0[1]+zc0[2]+zc0[3];
                float q0 = zc0[0]*zc0[0]+zc0[1]*zc0[1]+zc0[2]*zc0[2]+zc0[3]*zc0[3];
                float s1 = zc1[0]+zc1[1]+zc1[2]+zc1[3];
                float q1 = zc1[0]*zc1[0]+zc1[1]*zc1[1]+zc1[2]*zc1[2]+zc1[3]*zc1[3];
#pragma unroll
                for (int o = 16; o > 0; o >>= 1) {
                    s0 += __shfl_xor_sync(0xffffffffu, s0, o);
                    q0 += __shfl_xor_sync(0xffffffffu, q0, o);
                    s1 += __shfl_xor_sync(0xffffffffu, s1, o);
                    q1 += __shfl_xor_sync(0xffffffffu, q1, o);
                }
                float mu0 = s0 * (1.0f/128.0f), mu1 = s1 * (1.0f/128.0f);
                float rs0 = rsqrtf(q0 * (1.0f/128.0f) - mu0*mu0 + 1e-5f);
                float rs1 = rsqrtf(q1 * (1.0f/128.0f) - mu1*mu1 + 1e-5f);
                float4 n0, n1;
                n0.x=(zc0[0]-mu0)*rs0*g4.x+bq4.x; n0.y=(zc0[1]-mu0)*rs0*g4.y+bq4.y;
                n0.z=(zc0[2]-mu0)*rs0*g4.z+bq4.z; n0.w=(zc0[3]-mu0)*rs0*g4.w+bq4.w;
                n1.x=(zc1[0]-mu1)*rs1*g4.x+bq4.x; n1.y=(zc1[1]-mu1)*rs1*g4.y+bq4.y;
                n1.z=(zc1[2]-mu1)*rs1*g4.z+bq4.z; n1.w=(zc1[3]-mu1)*rs1*g4.w+bq4.w;
                *(float4*)(bufA + r0 * CD + j0) = n0;
                *(float4*)(bufA + (r0 + 1) * CD + j0) = n1;
            }
            __syncwarp();

            float o0[4], o1[4];
            stage_mm(bufA, wA, r0, j0, o0, o1);           // stage 1
            {
                float4 h0, h1;
                h0.x=siluf(o0[0]+u0.x); h0.y=siluf(o0[1]+u0.y);
                h0.z=siluf(o0[2]+u0.z); h0.w=siluf(o0[3]+u0.w);
                h1.x=siluf(o1[0]+u1.x); h1.y=siluf(o1[1]+u1.y);
                h1.z=siluf(o1[2]+u1.z); h1.w=siluf(o1[3]+u1.w);
                *(float4*)(bufB + r0 * CD + j0) = h0;
                *(float4*)(bufB + (r0 + 1) * CD + j0) = h1;
            }
            __syncwarp();
            stage_mm(bufB, wB, r0, j0, o0, o1);           // stage 2
            {
                float4 h0, h1;
                h0.x=siluf(o0[0]+b2v.x); h0.y=siluf(o0[1]+b2v.y);
                h0.z=siluf(o0[2]+b2v.z); h0.w=siluf(o0[3]+b2v.w);
                h1.x=siluf(o1[0]+b2v.x); h1.y=siluf(o1[1]+b2v.y);
                h1.z=siluf(o1[2]+b2v.z); h1.w=siluf(o1[3]+b2v.w);
                *(float4*)(bufA + r0 * CD + j0) = h0;
                *(float4*)(bufA + (r0 + 1) * CD + j0) = h1;
            }
            __syncwarp();
            stage_mm(bufA, wC, r0, j0, o0, o1);           // stage 3 -> k
            float k0v[4], k1v[4];
            k0v[0]=o0[0]+b3v.x; k0v[1]=o0[1]+b3v.y; k0v[2]=o0[2]+b3v.z; k0v[3]=o0[3]+b3v.w;
            k1v[0]=o1[0]+b3v.x; k1v[1]=o1[1]+b3v.y; k1v[2]=o1[2]+b3v.z; k1v[3]=o1[3]+b3v.w;

            if (e == 0) {
#pragma unroll
                for (int d = 0; d < 4; ++d) {
                    ac0[d]=k0v[d]; ac1[d]=k1v[d];
                    zc0[d]=zb0[d]+hdt*k0v[d]; zc1[d]=zb1[d]+hdt*k1v[d];
                }
            } else if (e == 1) {
#pragma unroll
                for (int d = 0; d < 4; ++d) {
                    ac0[d]+=2.0f*k0v[d]; ac1[d]+=2.0f*k1v[d];
                    zc0[d]=zb0[d]+hdt*k0v[d]; zc1[d]=zb1[d]+hdt*k1v[d];
                }
            } else if (e == 2) {
#pragma unroll
                for (int d = 0; d < 4; ++d) {
                    ac0[d]+=2.0f*k0v[d]; ac1[d]+=2.0f*k1v[d];
                    zc0[d]=zb0[d]+dt*k0v[d]; zc1[d]=zb1[d]+dt*k1v[d];
                }
            } else {
#pragma unroll
                for (int d = 0; d < 4; ++d) {
                    ac0[d]+=k0v[d]; ac1[d]+=k1v[d];
                    zb0[d]+=dt6*ac0[d]; zb1[d]+=dt6*ac1[d];
                    zc0[d]=zb0[d]; zc1[d]=zb1[d];
                }
            }
            __syncwarp();
        }
    }
    *(float4*)(g_z + (size_t)(b0 + r0) * CD + j0)     = make_float4(zb0[0],zb0[1],zb0[2],zb0[3]);
    *(float4*)(g_z + (size_t)(b0 + r0 + 1) * CD + j0) = make_float4(zb1[0],zb1[1],zb1[2],zb1[3]);
}

// ---------------- K3: concat [x_flat | cond | time_emb] ----------------
__global__ void build_in_kernel(const float* __restrict__ x_t, const int* __restrict__ tvec) {
    int b = blockIdx.x;
    int t = threadIdx.x;
    float* dst = g_hin + (size_t)b * INF;
    const float* src = x_t + (size_t)b * OUTF;
    for (int i = t; i < OUTF / 4; i += 256)
        ((float4*)dst)[i] = ((const float4*)src)[i];
    if (t < CD / 4)
        ((float4*)(dst + OUTF))[t] = ((const float4*)(g_z + (size_t)b * CD))[t];
    if (t < CD) {
        float tf = (float)tvec[b];
        int i = t & 63;
        float f = expf(-9.210340371976184f * (float)i / 63.0f);
        float arg = tf * f;
        dst[OUTF + CD + t] = (t < 64) ? sinf(arg) : cosf(arg);
    }
}

// ---------------- K4: tiled SGEMM  C = act(A @ W^T + bias) ----------------
template <bool SILU>
__global__ void __launch_bounds__(128) gemm_kernel(const float* __restrict__ A,
                                                   const float* __restrict__ W,
                                                   const float* __restrict__ bias,
                                                   float* __restrict__ C,
                                                   int M, int N, int K) {
    __shared__ float As[16][68];
    __shared__ float Ws[16][68];
    int t = threadIdx.x;
    int bm0 = blockIdx.y * 64, bn0 = blockIdx.x * 64;
    int tm = t >> 4, tn = t & 15;
    int m0 = tm * 8, n0 = tn * 4;
    float acc[8][4];
#pragma unroll
    for (int i = 0; i < 8; ++i) { acc[i][0]=acc[i][1]=acc[i][2]=acc[i][3]=0.f; }

    for (int k0 = 0; k0 < K; k0 += 16) {
#pragma unroll
        for (int it = 0; it < 2; ++it) {
            int r = it * 32 + (t >> 2);
            int c = (t & 3) * 4;
            float4 va = *(const float4*)(A + (size_t)(bm0 + r) * K + k0 + c);
            As[c+0][r]=va.x; As[c+1][r]=va.y; As[c+2][r]=va.z; As[c+3][r]=va.w;
            float4 vw = *(const float4*)(W + (size_t)(bn0 + r) * K + k0 + c);
            Ws[c+0][r]=vw.x; Ws[c+1][r]=vw.y; Ws[c+2][r]=vw.z; Ws[c+3][r]=vw.w;
        }
        __syncthreads();
#pragma unroll
        for (int kk = 0; kk < 16; ++kk) {
            float4 wv = *(const float4*)(&Ws[kk][n0]);
            float4 al = *(const float4*)(&As[kk][m0]);
            float4 ah = *(const float4*)(&As[kk][m0 + 4]);
            float a_[8] = { al.x, al.y, al.z, al.w, ah.x, ah.y, ah.z, ah.w };
#pragma unroll
            for (int i = 0; i < 8; ++i) {
                acc[i][0] = fmaf(a_[i], wv.x, acc[i][0]);
                acc[i][1] = fmaf(a_[i], wv.y, acc[i][1]);
                acc[i][2] = fmaf(a_[i], wv.z, acc[i][2]);
                acc[i][3] = fmaf(a_[i], wv.w, acc[i][3]);
            }
        }
        __syncthreads();
    }
    float4 bv = *(const float4*)(bias + bn0 + n0);
#pragma unroll
    for (int i = 0; i < 8; ++i) {
        float4 o;
        o.x = acc[i][0] + bv.x; o.y = acc[i][1] + bv.y;
        o.z = acc[i][2] + bv.z; o.w = acc[i][3] + bv.w;
        if (SILU) {
            o.x = siluf(o.x); o.y = siluf(o.y); o.z = siluf(o.z); o.w = siluf(o.w);
        }
        *(float4*)(C + (size_t)(bm0 + m0 + i) * N + bn0 + n0) = o;
    }
}

// ---------------- launch ----------------
extern "C" void kernel_launch(void* const* d_in, const int* in_sizes, int n_in,
                              void* d_out, int out_size) {
    const float* x_t  = (const float*)d_in[0];
    const float* past = (const float*)d_in[1];
    const int*   tv   = (const int*)d_in[2];
    const float* xpw  = (const float*)d_in[3];
    const float* xpb  = (const float*)d_in[4];
    const float* z0w  = (const float*)d_in[5];
    const float* z0b  = (const float*)d_in[6];
    const float* lng  = (const float*)d_in[7];
    const float* lnb  = (const float*)d_in[8];
    const float* w1   = (const float*)d_in[9];
    const float* b1   = (const float*)d_in[10];
    const float* w2   = (const float*)d_in[11];
    const float* b2   = (const float*)d_in[12];
    const float* w3   = (const float*)d_in[13];
    const float* b3   = (const float*)d_in[14];
    const float* fw1  = (const float*)d_in[15];
    const float* fb1  = (const float*)d_in[16];
    const float* fw2  = (const float*)d_in[17];
    const float* fb2  = (const float*)d_in[18];
    const float* fw3  = (const float*)d_in[19];
    const float* fb3  = (const float*)d_in[20];
    float* out = (float*)d_out;

    static int smem_set = 0;
    if (!smem_set) {
        cudaFuncSetAttribute(ode_kernel, cudaFuncAttributeMaxDynamicSharedMemorySize, ODE_SMEM_BYTES);
        smem_set = 1;
    }

    fold_kernel<<<8, 256>>>(w1, b1, xpw, xpb, z0w, z0b);
    interp_proj_kernel<<<dim3(32, NT + 1), 256>>>(past);
    ode_kernel<<<BATCH / 16, 256, ODE_SMEM_BYTES>>>(w1, w2, b2, w3, b3, lng, lnb);
    build_in_kernel<<<BATCH, 256>>>(x_t, tv);

    float* h1p; cudaGetSymbolAddress((void**)&h1p, g_h1);
    float* h2p; cudaGetSymbolAddress((void**)&h2p, g_h2);
    float* hinp; cudaGetSymbolAddress((void**)&hinp, g_hin);

    gemm_kernel<true ><<<dim3(HIDF / 64, BATCH / 64), 128>>>(hinp, fw1, fb1, h1p, BATCH, HIDF, INF);
    gemm_kernel<true ><<<dim3(HIDF / 64, BATCH / 64), 128>>>(h1p,  fw2, fb2, h2p, BATCH, HIDF, HIDF);
    gemm_kernel<false><<<dim3(OUTF / 64, BATCH / 64), 128>>>(h2p,  fw3, fb3, out, BATCH, OUTF, HIDF);
}